// round 1
// baseline (speedup 1.0000x reference)
#include <cuda_runtime.h>
#include <math.h>

// Problem constants
#define BB   2
#define SS   2048
#define DD   1024
#define HH   16
#define DK   64
#define VV   4096
#define NZ   10
#define BH   (BB*HH)      // 32
#define MROWS (BB*SS)     // 4096

// ---------------- scratch (device globals: allocation-free) ----------------
__device__ float g_q   [MROWS*DD];            // 16 MB
__device__ float g_k   [MROWS*DD];            // 16 MB
__device__ float g_v   [MROWS*DD];            // 16 MB
__device__ float g_ao  [MROWS*DD];            // 16 MB
__device__ float g_sband[BH*SS*128];          // 32 MB  (banded scores)
__device__ float g_attn[134217728];           // 512 MB (BH*SS*SS)

// ---------------- generic NT GEMM with bias: C[m,n] = sum_k A[m,k]B[n,k] + bias[n]
// 64x64 tile, 256 threads, 4x4 per thread, K-step 16. M,N multiples of 64; K of 16.
__global__ void gemm_nt_bias(const float* __restrict__ A, const float* __restrict__ B,
                             const float* __restrict__ bias, float* __restrict__ C,
                             int M, int N, int K) {
    __shared__ float As[16][65];
    __shared__ float Bs[16][65];
    int t  = threadIdx.x;
    int tx = t & 15, ty = t >> 4;
    int m0 = blockIdx.y * 64, n0 = blockIdx.x * 64;
    float acc[4][4] = {};
    for (int k0 = 0; k0 < K; k0 += 16) {
#pragma unroll
        for (int r = 0; r < 4; r++) {
            int idx = t + r * 256;           // 0..1023
            int mm = idx >> 4, kk = idx & 15;
            As[kk][mm] = A[(size_t)(m0 + mm) * K + k0 + kk];
            Bs[kk][mm] = B[(size_t)(n0 + mm) * K + k0 + kk];
        }
        __syncthreads();
#pragma unroll
        for (int kk = 0; kk < 16; kk++) {
            float a[4], b[4];
#pragma unroll
            for (int r = 0; r < 4; r++) a[r] = As[kk][ty * 4 + r];
#pragma unroll
            for (int c = 0; c < 4; c++) b[c] = Bs[kk][tx * 4 + c];
#pragma unroll
            for (int r = 0; r < 4; r++)
#pragma unroll
                for (int c = 0; c < 4; c++) acc[r][c] += a[r] * b[c];
        }
        __syncthreads();
    }
#pragma unroll
    for (int r = 0; r < 4; r++) {
        int m = m0 + ty * 4 + r;
#pragma unroll
        for (int c = 0; c < 4; c++) {
            int n = n0 + tx * 4 + c;
            C[(size_t)m * N + n] = acc[r][c] + bias[n];
        }
    }
}

// ---------------- banded QK scores: tiles with |it - jt| <= 1 only ----------------
// grid: (x in {0,1} = it - jt, y = it, z = bh). Output -> g_sband[bh][i][j - (it-1)*64]
__global__ void scores_kernel(const float* __restrict__ gamma,
                              const int*   __restrict__ ids,
                              const float* __restrict__ omega) {
    int x  = blockIdx.x;
    int it = blockIdx.y;
    int bh = blockIdx.z;
    if (x == 1 && it == 0) return;
    int b = bh / HH, h = bh % HH;
    int i0 = it * 64;
    int j0 = (it - x) * 64;

    __shared__ float Mtab[128];
    __shared__ float As[16][65];
    __shared__ float Bs[16][65];
    __shared__ int   idi[64], idj[64];

    int t  = threadIdx.x;
    int tx = t & 15, ty = t >> 4;

    if (t < 128) {
        float d  = (float)t;
        float ls = logf(d + 1.0f);
        float cs = 0.0f;
#pragma unroll
        for (int z = 0; z < NZ; z++) cs += cosf(gamma[z] * ls);
        Mtab[t] = expf(-d) * cs;
    }
    if (t < 64) {
        idi[t] = ids[b * SS + i0 + t];
        idj[t] = ids[b * SS + j0 + t];
    }

    const float* Aq = g_q + (size_t)(b * SS + i0) * DD + h * DK;
    const float* Bk = g_k + (size_t)(b * SS + j0) * DD + h * DK;

    float acc[4][4] = {};
    for (int k0 = 0; k0 < DK; k0 += 16) {
        __syncthreads();
#pragma unroll
        for (int r = 0; r < 4; r++) {
            int idx = t + r * 256;
            int mm = idx >> 4, kk = idx & 15;
            As[kk][mm] = Aq[(size_t)mm * DD + k0 + kk];
            Bs[kk][mm] = Bk[(size_t)mm * DD + k0 + kk];
        }
        __syncthreads();
#pragma unroll
        for (int kk = 0; kk < 16; kk++) {
            float a[4], bv[4];
#pragma unroll
            for (int r = 0; r < 4; r++) a[r] = As[kk][ty * 4 + r];
#pragma unroll
            for (int c = 0; c < 4; c++) bv[c] = Bs[kk][tx * 4 + c];
#pragma unroll
            for (int r = 0; r < 4; r++)
#pragma unroll
                for (int c = 0; c < 4; c++) acc[r][c] += a[r] * bv[c];
        }
    }
    __syncthreads();

    int coff = (1 - x) * 64;  // column offset within the 128-wide band window
#pragma unroll
    for (int r = 0; r < 4; r++) {
        int il = ty * 4 + r;
        int i  = i0 + il;
        float* dst = &g_sband[((size_t)bh * SS + i) * 128];
#pragma unroll
        for (int c = 0; c < 4; c++) {
            int jl = tx * 4 + c;
            int j  = j0 + jl;
            int ad = i - j; if (ad < 0) ad = -ad;            // < 128 in band
            float s = acc[r][c] * 0.125f * Mtab[ad];
            if (omega[(size_t)idi[il] * VV + idj[jl]] == 0.0f) s = -1.0e9f;
            dst[coff + jl] = s;
        }
    }
}

// ---------------- softmax: one block per (bh, i). Far j: score = 0 / -1e9 from omega.
__global__ void softmax_kernel(const int* __restrict__ ids,
                               const float* __restrict__ omega) {
    int i  = blockIdx.x;
    int bh = blockIdx.y;
    int b  = bh / HH;
    int t  = threadIdx.x;

    __shared__ float omg[VV];   // 16 KB: omega row for id_i
    __shared__ int   idr[SS];   // 8 KB : token ids for batch b
    __shared__ float red[256];

    int id_i = ids[b * SS + i];
    for (int d = t; d < VV; d += 256) omg[d] = omega[(size_t)id_i * VV + d];
    for (int j = t; j < SS; j += 256) idr[j] = ids[b * SS + j];
    __syncthreads();

    int bandlo = (i >> 6) * 64 - 64;
    const float* sb = &g_sband[((size_t)bh * SS + i) * 128];

    // max over j <= i
    float m = -1.0e9f;
    for (int j = t; j <= i; j += 256) {
        float s = (j >= bandlo) ? sb[j - bandlo]
                                : (omg[idr[j]] != 0.0f ? 0.0f : -1.0e9f);
        m = fmaxf(m, s);
    }
    red[t] = m; __syncthreads();
    for (int o = 128; o > 0; o >>= 1) {
        if (t < o) red[t] = fmaxf(red[t], red[t + o]);
        __syncthreads();
    }
    m = red[0];
    __syncthreads();

    // sum
    float zs = 0.0f;
    for (int j = t; j <= i; j += 256) {
        float s = (j >= bandlo) ? sb[j - bandlo]
                                : (omg[idr[j]] != 0.0f ? 0.0f : -1.0e9f);
        zs += expf(s - m);
    }
    red[t] = zs; __syncthreads();
    for (int o = 128; o > 0; o >>= 1) {
        if (t < o) red[t] += red[t + o];
        __syncthreads();
    }
    float wu  = expf(-1.0e9f - m);                 // 0 normally; 1 if fully masked row
    float Z   = red[0] + (float)(SS - 1 - i) * wu; // upper-triangle entries
    float inv = 1.0f / Z;

    float* arow = &g_attn[((size_t)bh * SS + i) * SS];
    for (int j = t; j < SS; j += 256) {
        float a;
        if (j <= i) {
            float s = (j >= bandlo) ? sb[j - bandlo]
                                    : (omg[idr[j]] != 0.0f ? 0.0f : -1.0e9f);
            a = expf(s - m) * inv;
        } else {
            a = wu * inv;
        }
        arow[j] = a;
    }
}

// ---------------- PV: per (bh): out[m, hd] = sum_k attn[m,k] * v[k, h*64+hd] ----------------
__global__ void pv_kernel() {
    int mt = blockIdx.y;
    int bh = blockIdx.z;
    int b  = bh / HH, h = bh % HH;
    __shared__ float As[16][65];
    __shared__ float Bs[16][65];
    int t  = threadIdx.x;
    int tx = t & 15, ty = t >> 4;
    int m0 = mt * 64;

    const float* A  = &g_attn[(size_t)bh * SS * SS];
    const float* Bv = g_v + (size_t)b * SS * DD + h * DK;

    float acc[4][4] = {};
    for (int k0 = 0; k0 < SS; k0 += 16) {
#pragma unroll
        for (int r = 0; r < 4; r++) {
            int idx = t + r * 256;
            int mm  = idx >> 4, kk = idx & 15;
            As[kk][mm] = A[(size_t)(m0 + mm) * SS + k0 + kk];
            int kk2 = idx >> 6, nn = idx & 63;
            Bs[kk2][nn] = Bv[(size_t)(k0 + kk2) * DD + nn];
        }
        __syncthreads();
#pragma unroll
        for (int kk = 0; kk < 16; kk++) {
            float a[4], bb[4];
#pragma unroll
            for (int r = 0; r < 4; r++) a[r] = As[kk][ty * 4 + r];
#pragma unroll
            for (int c = 0; c < 4; c++) bb[c] = Bs[kk][tx * 4 + c];
#pragma unroll
            for (int r = 0; r < 4; r++)
#pragma unroll
                for (int c = 0; c < 4; c++) acc[r][c] += a[r] * bb[c];
        }
        __syncthreads();
    }

    float* C = g_ao + (size_t)b * SS * DD + h * DK;
#pragma unroll
    for (int r = 0; r < 4; r++)
#pragma unroll
        for (int c = 0; c < 4; c++)
            C[(size_t)(m0 + ty * 4 + r) * DD + tx * 4 + c] = acc[r][c];
}

// ---------------- launcher ----------------
extern "C" void kernel_launch(void* const* d_in, const int* in_sizes, int n_in,
                              void* d_out, int out_size) {
    const float* x     = (const float*)d_in[0];
    const float* wq    = (const float*)d_in[1];
    const float* bq    = (const float*)d_in[2];
    const float* wk    = (const float*)d_in[3];
    const float* bk    = (const float*)d_in[4];
    const float* wv    = (const float*)d_in[5];
    const float* bv    = (const float*)d_in[6];
    const float* wo    = (const float*)d_in[7];
    const float* bo    = (const float*)d_in[8];
    const float* omega = (const float*)d_in[9];
    const float* gamma = (const float*)d_in[10];
    const int*   ids   = (const int*)d_in[11];
    // d_in[12] = causal_mask (tril by construction; not needed)
    float* out = (float*)d_out;

    float *pq, *pk, *pv;
    cudaGetSymbolAddress((void**)&pq, g_q);
    cudaGetSymbolAddress((void**)&pk, g_k);
    cudaGetSymbolAddress((void**)&pv, g_v);
    float* pao;
    cudaGetSymbolAddress((void**)&pao, g_ao);

    dim3 blk(256);
    dim3 gproj(DD / 64, MROWS / 64);   // (16, 64)

    // Q, K, V projections
    gemm_nt_bias<<<gproj, blk>>>(x, wq, bq, pq, MROWS, DD, DD);
    gemm_nt_bias<<<gproj, blk>>>(x, wk, bk, pk, MROWS, DD, DD);
    gemm_nt_bias<<<gproj, blk>>>(x, wv, bv, pv, MROWS, DD, DD);

    // Banded scores (QK * M * masks)
    dim3 gsc(2, SS / 64, BH);          // (2, 32, 32)
    scores_kernel<<<gsc, blk>>>(gamma, ids, omega);

    // Softmax -> full attn matrix
    dim3 gsm(SS, BH);                  // (2048, 32)
    softmax_kernel<<<gsm, blk>>>(ids, omega);

    // PV
    dim3 gpv(1, SS / 64, BH);          // (1, 32, 32)
    pv_kernel<<<gpv, blk>>>();

    // Output projection
    gemm_nt_bias<<<gproj, blk>>>(pao, wo, bo, out, MROWS, DD, DD);
}

// round 2
// speedup vs baseline: 2.4405x; 2.4405x over previous
#include <cuda_runtime.h>
#include <math.h>

// Problem constants
#define BB   2
#define SS   2048
#define DD   1024
#define HH   16
#define DK   64
#define VV   4096
#define NZ   10
#define BH   (BB*HH)      // 32
#define MROWS (BB*SS)     // 4096

// ---------------- scratch (device globals: allocation-free) ----------------
__device__ float g_q   [MROWS*DD];                 // 16 MB
__device__ float g_k   [MROWS*DD];                 // 16 MB
__device__ float g_v   [MROWS*DD];                 // 16 MB
__device__ float g_ao  [MROWS*DD];                 // 16 MB
__device__ float g_sband[BH*SS*128];               // 32 MB (banded scores)
__device__ float g_pref [(size_t)BB*(SS+1)*DD];    // 16.8 MB (exclusive prefix of v)
__device__ float g_csum [BB*8*DD];                 // chunk sums
__device__ float g_msum [(size_t)BB*SS*DD];        // 16 MB masked-far v sums
__device__ int   g_mcnt [BB*SS];                   // masked-far counts

// =============== 128x128 SGEMM (NT, +bias): C[m,n] = sum_k A[m,k]B[n,k]+bias[n]
// 256 threads, 8x8 per thread, K-step 16, register prefetch.
__global__ __launch_bounds__(256, 2)
void gemm128(const float* __restrict__ A, const float* __restrict__ Bw,
             const float* __restrict__ bias, float* __restrict__ C,
             int K, int N) {
    __shared__ float As[16][132];
    __shared__ float Bs[16][132];
    int t  = threadIdx.x;
    int m0 = blockIdx.y * 128, n0 = blockIdx.x * 128;
    int lrow = t >> 2;            // 0..63
    int lk   = (t & 3) * 4;       // 0,4,8,12

    const float* Ap = A  + (size_t)(m0 + lrow) * K + lk;
    const float* Bp = Bw + (size_t)(n0 + lrow) * K + lk;
    float4 pa0 = *(const float4*)Ap;
    float4 pa1 = *(const float4*)(Ap + (size_t)64 * K);
    float4 pb0 = *(const float4*)Bp;
    float4 pb1 = *(const float4*)(Bp + (size_t)64 * K);

    int tx = t & 15, ty = t >> 4;
    float acc[8][8] = {};

    for (int k0 = 0; k0 < K; k0 += 16) {
        __syncthreads();
        As[lk+0][lrow] = pa0.x; As[lk+1][lrow] = pa0.y;
        As[lk+2][lrow] = pa0.z; As[lk+3][lrow] = pa0.w;
        As[lk+0][lrow+64] = pa1.x; As[lk+1][lrow+64] = pa1.y;
        As[lk+2][lrow+64] = pa1.z; As[lk+3][lrow+64] = pa1.w;
        Bs[lk+0][lrow] = pb0.x; Bs[lk+1][lrow] = pb0.y;
        Bs[lk+2][lrow] = pb0.z; Bs[lk+3][lrow] = pb0.w;
        Bs[lk+0][lrow+64] = pb1.x; Bs[lk+1][lrow+64] = pb1.y;
        Bs[lk+2][lrow+64] = pb1.z; Bs[lk+3][lrow+64] = pb1.w;
        __syncthreads();
        if (k0 + 16 < K) {
            Ap += 16; Bp += 16;
            pa0 = *(const float4*)Ap;
            pa1 = *(const float4*)(Ap + (size_t)64 * K);
            pb0 = *(const float4*)Bp;
            pb1 = *(const float4*)(Bp + (size_t)64 * K);
        }
#pragma unroll
        for (int kk = 0; kk < 16; kk++) {
            float4 a0 = *(const float4*)&As[kk][ty*8];
            float4 a1 = *(const float4*)&As[kk][ty*8+4];
            float4 b0 = *(const float4*)&Bs[kk][tx*8];
            float4 b1 = *(const float4*)&Bs[kk][tx*8+4];
            float av[8] = {a0.x,a0.y,a0.z,a0.w,a1.x,a1.y,a1.z,a1.w};
            float bv[8] = {b0.x,b0.y,b0.z,b0.w,b1.x,b1.y,b1.z,b1.w};
#pragma unroll
            for (int r = 0; r < 8; r++)
#pragma unroll
                for (int c = 0; c < 8; c++) acc[r][c] += av[r] * bv[c];
        }
    }

    float bb[8];
#pragma unroll
    for (int c = 0; c < 8; c++) bb[c] = bias[n0 + tx*8 + c];
#pragma unroll
    for (int r = 0; r < 8; r++) {
        int row = m0 + ty*8 + r;
        float4 o0 = {acc[r][0]+bb[0], acc[r][1]+bb[1], acc[r][2]+bb[2], acc[r][3]+bb[3]};
        float4 o1 = {acc[r][4]+bb[4], acc[r][5]+bb[5], acc[r][6]+bb[6], acc[r][7]+bb[7]};
        *(float4*)&C[(size_t)row * N + n0 + tx*8]     = o0;
        *(float4*)&C[(size_t)row * N + n0 + tx*8 + 4] = o1;
    }
}

// =============== banded QK scores (unchanged) ===============
__global__ void scores_kernel(const float* __restrict__ gamma,
                              const int*   __restrict__ ids,
                              const float* __restrict__ omega) {
    int x  = blockIdx.x;
    int it = blockIdx.y;
    int bh = blockIdx.z;
    if (x == 1 && it == 0) return;
    int b = bh / HH, h = bh % HH;
    int i0 = it * 64;
    int j0 = (it - x) * 64;

    __shared__ float Mtab[128];
    __shared__ float As[16][65];
    __shared__ float Bs[16][65];
    __shared__ int   idi[64], idj[64];

    int t  = threadIdx.x;
    int tx = t & 15, ty = t >> 4;

    if (t < 128) {
        float d  = (float)t;
        float ls = logf(d + 1.0f);
        float cs = 0.0f;
#pragma unroll
        for (int z = 0; z < NZ; z++) cs += cosf(gamma[z] * ls);
        Mtab[t] = expf(-d) * cs;
    }
    if (t < 64) {
        idi[t] = ids[b * SS + i0 + t];
        idj[t] = ids[b * SS + j0 + t];
    }

    const float* Aq = g_q + (size_t)(b * SS + i0) * DD + h * DK;
    const float* Bk = g_k + (size_t)(b * SS + j0) * DD + h * DK;

    float acc[4][4] = {};
    for (int k0 = 0; k0 < DK; k0 += 16) {
        __syncthreads();
#pragma unroll
        for (int r = 0; r < 4; r++) {
            int idx = t + r * 256;
            int mm = idx >> 4, kk = idx & 15;
            As[kk][mm] = Aq[(size_t)mm * DD + k0 + kk];
            Bs[kk][mm] = Bk[(size_t)mm * DD + k0 + kk];
        }
        __syncthreads();
#pragma unroll
        for (int kk = 0; kk < 16; kk++) {
            float a[4], bv[4];
#pragma unroll
            for (int r = 0; r < 4; r++) a[r] = As[kk][ty * 4 + r];
#pragma unroll
            for (int c = 0; c < 4; c++) bv[c] = Bs[kk][tx * 4 + c];
#pragma unroll
            for (int r = 0; r < 4; r++)
#pragma unroll
                for (int c = 0; c < 4; c++) acc[r][c] += a[r] * bv[c];
        }
    }
    __syncthreads();

    int coff = (1 - x) * 64;
#pragma unroll
    for (int r = 0; r < 4; r++) {
        int il = ty * 4 + r;
        int i  = i0 + il;
        float* dst = &g_sband[((size_t)bh * SS + i) * 128];
#pragma unroll
        for (int c = 0; c < 4; c++) {
            int jl = tx * 4 + c;
            int j  = j0 + jl;
            int ad = i - j; if (ad < 0) ad = -ad;
            float s = acc[r][c] * 0.125f * Mtab[ad];
            if (omega[(size_t)idi[il] * VV + idj[jl]] == 0.0f) s = -1.0e9f;
            dst[coff + jl] = s;
        }
    }
}

// =============== V chunk sums (for prefix) ===============
__global__ void vchunk_kernel() {
    int b  = blockIdx.x;          // 0..1
    int ch = blockIdx.y;          // 0..7
    int dc = blockIdx.z;          // 0..3
    int d  = dc * 256 + threadIdx.x;
    float acc = 0.0f;
    const float* base = g_v + ((size_t)b * SS + ch * 256) * DD + d;
#pragma unroll 8
    for (int j = 0; j < 256; j++) acc += base[(size_t)j * DD];
    g_csum[((size_t)b * 8 + ch) * DD + d] = acc;
}

// =============== V prefix sums: g_pref[b][j][d] = sum_{j'<j} v ===============
__global__ void vpref_kernel() {
    int b  = blockIdx.x;
    int ch = blockIdx.y;
    int dc = blockIdx.z;
    int d  = dc * 256 + threadIdx.x;
    float acc = 0.0f;
    for (int c = 0; c < ch; c++) acc += g_csum[((size_t)b * 8 + c) * DD + d];
    const float* vbase = g_v + ((size_t)b * SS + ch * 256) * DD + d;
    float* pbase = g_pref + ((size_t)b * (SS + 1) + ch * 256) * DD + d;
    for (int j = 0; j < 256; j++) {
        pbase[(size_t)j * DD] = acc;
        acc += vbase[(size_t)j * DD];
    }
    if (ch == 7) g_pref[((size_t)b * (SS + 1) + SS) * DD + d] = acc;
}

// =============== far scan: masked-far count + masked v-sum per (b,i) ===============
__global__ void farscan_kernel(const int* __restrict__ ids,
                               const float* __restrict__ omega) {
    int i = blockIdx.x;
    int b = blockIdx.y;
    int t = threadIdx.x;
    int lo = (i >> 6) * 64 - 64;
    int bandlo = lo < 0 ? 0 : lo;

    __shared__ float omg[VV];     // 16 KB
    __shared__ int   list[1024];
    __shared__ int   cnt;

    int id_i = ids[b * SS + i];
    for (int dd = t; dd < VV; dd += 256) omg[dd] = omega[(size_t)id_i * VV + dd];
    if (t == 0) cnt = 0;
    __syncthreads();

    for (int j = t; j < bandlo; j += 256) {
        int idj = ids[b * SS + j];
        if (omg[idj] == 0.0f) {
            int p = atomicAdd(&cnt, 1);
            if (p < 1024) list[p] = j;
        }
    }
    __syncthreads();
    int n = cnt; if (n > 1024) n = 1024;

    float acc0 = 0.f, acc1 = 0.f, acc2 = 0.f, acc3 = 0.f;
    for (int l = 0; l < n; l++) {
        const float* vr = g_v + ((size_t)b * SS + list[l]) * DD;
        acc0 += vr[t];
        acc1 += vr[t + 256];
        acc2 += vr[t + 512];
        acc3 += vr[t + 768];
    }
    float* ms = g_msum + ((size_t)b * SS + i) * DD;
    ms[t]       = acc0;
    ms[t + 256] = acc1;
    ms[t + 512] = acc2;
    ms[t + 768] = acc3;
    if (t == 0) g_mcnt[b * SS + i] = n;
}

// =============== fused band softmax + band PV + far/tail correction ===============
extern __shared__ float dynsmem[];
__global__ void bandpv_kernel() {
    float* Sc = dynsmem;              // [128][68]  weights (transposed: [cc][r])
    float* Vb = dynsmem + 128 * 68;   // [128][68]  v band rows
    __shared__ float red[256];
    __shared__ float m_s[64], inv_s[64], c0_s[64], wr_s[64];
    __shared__ float prefLo[64];

    int it = blockIdx.x;   // 0..31
    int bh = blockIdx.y;   // 0..31
    int b = bh >> 4, h = bh & 15;
    int lo_raw = it * 64 - 64;
    int bandlo = lo_raw < 0 ? 0 : lo_raw;
    int t = threadIdx.x;

    // load band scores (transpose), invalidating j<0 and j>i
    for (int idx = t; idx < 8192; idx += 256) {
        int r = idx >> 7, cc = idx & 127;
        int i = it * 64 + r;
        int j = lo_raw + cc;
        float s = -3.0e38f;
        if (j >= 0 && j <= i) s = g_sband[((size_t)bh * SS + i) * 128 + cc];
        Sc[cc * 68 + r] = s;
    }
    // load V band slice
    for (int idx = t; idx < 8192; idx += 256) {
        int cc = idx >> 6, d = idx & 63;
        int j = lo_raw + cc;
        float vv = 0.0f;
        if (j >= 0) vv = g_v[((size_t)(b * SS + j)) * DD + h * 64 + d];
        Vb[cc * 68 + d] = vv;
    }
    if (t < 64) prefLo[t] = g_pref[((size_t)b * (SS + 1) + bandlo) * DD + h * 64 + t];
    __syncthreads();

    // per-row max
    int r = t & 63, q = t >> 6;
    float mx = -3.0e38f;
    for (int cc = q; cc < 128; cc += 4) mx = fmaxf(mx, Sc[cc * 68 + r]);
    red[t] = mx;
    __syncthreads();
    if (t < 64) {
        float m = fmaxf(fmaxf(red[r], red[64 + r]), fmaxf(red[128 + r], red[192 + r]));
        int i = it * 64 + r;
        int af = bandlo - g_mcnt[b * SS + i];
        if (af > 0) m = fmaxf(m, 0.0f);
        m_s[r] = m;
    }
    __syncthreads();

    // per-row sum
    float m = m_s[r];
    float zs = 0.0f;
    for (int cc = q; cc < 128; cc += 4) zs += expf(Sc[cc * 68 + r] - m);
    red[t] = zs;
    __syncthreads();
    if (t < 64) {
        float bsum = red[r] + red[64 + r] + red[128 + r] + red[192 + r];
        int i  = it * 64 + r;
        int mc = g_mcnt[b * SS + i];
        int af = bandlo - mc;
        float m0 = m_s[r];
        float wu = expf(-1.0e9f - m0);         // 0 normally, 1 on degenerate rows
        float Z  = bsum + (af > 0 ? (float)af * expf(-m0) : 0.0f)
                        + (float)(mc + (SS - 1 - i)) * wu;
        float inv = 1.0f / Z;
        inv_s[r] = inv;
        c0_s[r]  = (af > 0) ? expf(-m0) * inv : 0.0f;
        wr_s[r]  = wu * inv;
    }
    __syncthreads();

    // convert scores -> weights in place
    for (int idx = t; idx < 8192; idx += 256) {
        int cc = idx >> 6, rr = idx & 63;
        Sc[cc * 68 + rr] = expf(Sc[cc * 68 + rr] - m_s[rr]) * inv_s[rr];
    }
    __syncthreads();

    // 64x64x128 mini-GEMM: out[r][d] = sum_cc W[cc][r] * Vb[cc][d]
    int tx = t & 15, ty = t >> 4;
    float acc[4][4] = {};
#pragma unroll 4
    for (int cc = 0; cc < 128; cc++) {
        float4 w4 = *(const float4*)&Sc[cc * 68 + ty * 4];
        float4 v4 = *(const float4*)&Vb[cc * 68 + tx * 4];
        float wv[4] = {w4.x, w4.y, w4.z, w4.w};
        float vv[4] = {v4.x, v4.y, v4.z, v4.w};
#pragma unroll
        for (int rr = 0; rr < 4; rr++)
#pragma unroll
            for (int c = 0; c < 4; c++) acc[rr][c] += wv[rr] * vv[c];
    }

    // epilogue: far + tail corrections
    const float* tv = g_pref + ((size_t)b * (SS + 1) + SS) * DD + h * 64;
#pragma unroll
    for (int rr = 0; rr < 4; rr++) {
        int rloc = ty * 4 + rr;
        int i = it * 64 + rloc;
        const float* ms = g_msum + ((size_t)b * SS + i) * DD + h * 64;
        const float* ph = g_pref + ((size_t)b * (SS + 1) + i + 1) * DD + h * 64;
        float c0 = c0_s[rloc], wr = wr_s[rloc];
        float* outp = g_ao + ((size_t)(b * SS + i)) * DD + h * 64;
#pragma unroll
        for (int c = 0; c < 4; c++) {
            int d = tx * 4 + c;
            float msv = ms[d];
            outp[d] = acc[rr][c] + c0 * (prefLo[d] - msv)
                                 + wr * (msv + tv[d] - ph[d]);
        }
    }
}

// ---------------- launcher ----------------
extern "C" void kernel_launch(void* const* d_in, const int* in_sizes, int n_in,
                              void* d_out, int out_size) {
    const float* x     = (const float*)d_in[0];
    const float* wq    = (const float*)d_in[1];
    const float* bq    = (const float*)d_in[2];
    const float* wk    = (const float*)d_in[3];
    const float* bk    = (const float*)d_in[4];
    const float* wv    = (const float*)d_in[5];
    const float* bv    = (const float*)d_in[6];
    const float* wo    = (const float*)d_in[7];
    const float* bo    = (const float*)d_in[8];
    const float* omega = (const float*)d_in[9];
    const float* gamma = (const float*)d_in[10];
    const int*   ids   = (const int*)d_in[11];
    float* out = (float*)d_out;

    float *pq, *pk, *pv, *pao;
    cudaGetSymbolAddress((void**)&pq,  g_q);
    cudaGetSymbolAddress((void**)&pk,  g_k);
    cudaGetSymbolAddress((void**)&pv,  g_v);
    cudaGetSymbolAddress((void**)&pao, g_ao);

    cudaFuncSetAttribute(bandpv_kernel,
                         cudaFuncAttributeMaxDynamicSharedMemorySize,
                         2 * 128 * 68 * (int)sizeof(float));

    dim3 blk(256);
    dim3 gproj(DD / 128, MROWS / 128);   // (8, 32)

    // Q, K, V projections
    gemm128<<<gproj, blk>>>(x, wq, bq, pq, DD, DD);
    gemm128<<<gproj, blk>>>(x, wk, bk, pk, DD, DD);
    gemm128<<<gproj, blk>>>(x, wv, bv, pv, DD, DD);

    // Banded scores
    dim3 gsc(2, SS / 64, BH);
    scores_kernel<<<gsc, blk>>>(gamma, ids, omega);

    // V prefix sums
    vchunk_kernel<<<dim3(BB, 8, 4), blk>>>();
    vpref_kernel <<<dim3(BB, 8, 4), blk>>>();

    // Far-mask scan
    farscan_kernel<<<dim3(SS, BB), blk>>>(ids, omega);

    // Fused band softmax + PV + far/tail corrections
    bandpv_kernel<<<dim3(SS / 64, BH), blk, 2 * 128 * 68 * sizeof(float)>>>();

    // Output projection
    gemm128<<<gproj, blk>>>(pao, wo, bo, out, DD, DD);
}

// round 4
// speedup vs baseline: 3.5049x; 1.4361x over previous
#include <cuda_runtime.h>
#include <cuda_bf16.h>
#include <mma.h>
#include <math.h>
#include <stdint.h>

using namespace nvcuda;

// Problem constants
#define BB   2
#define SS   2048
#define DD   1024
#define HH   16
#define DK   64
#define VV   4096
#define NZ   10
#define BH   (BB*HH)      // 32
#define MROWS (BB*SS)     // 4096

// ---------------- scratch (device globals: allocation-free) ----------------
__device__ float g_q   [MROWS*DD];                 // 16 MB
__device__ float g_k   [MROWS*DD];                 // 16 MB
__device__ float g_v   [MROWS*DD];                 // 16 MB
__device__ float g_ao  [MROWS*DD];                 // 16 MB
__device__ float g_sband[BH*SS*128];               // 32 MB (banded scores)
__device__ float g_pref [(size_t)BB*(SS+1)*DD];    // 16.8 MB (exclusive prefix of v)
__device__ float g_csum [BB*8*DD];                 // chunk sums
__device__ float g_msum [(size_t)BB*SS*DD];        // 16 MB masked-far v sums
__device__ int   g_mcnt [BB*SS];                   // masked-far counts

// split bf16 hi/lo copies
__device__ __nv_bfloat16 g_xhi [MROWS*DD];         // 8 MB
__device__ __nv_bfloat16 g_xlo [MROWS*DD];         // 8 MB
__device__ __nv_bfloat16 g_whi [4*DD*DD];          // 8 MB (wq,wk,wv,wo stacked)
__device__ __nv_bfloat16 g_wlo [4*DD*DD];          // 8 MB
__device__ __nv_bfloat16 g_aohi[MROWS*DD];         // 8 MB
__device__ __nv_bfloat16 g_aolo[MROWS*DD];         // 8 MB

__device__ __forceinline__ uint32_t pack_bf2(__nv_bfloat16 a, __nv_bfloat16 b) {
    return ((uint32_t)__bfloat16_as_ushort(b) << 16) | (uint32_t)__bfloat16_as_ushort(a);
}

// =============== split fp32 -> bf16 hi + bf16 lo ===============
__global__ void split_kernel(const float* __restrict__ in,
                             __nv_bfloat16* __restrict__ hi,
                             __nv_bfloat16* __restrict__ lo, int n4) {
    int i = blockIdx.x * blockDim.x + threadIdx.x;
    if (i >= n4) return;
    float4 v = ((const float4*)in)[i];
    __nv_bfloat16 h0 = __float2bfloat16(v.x), h1 = __float2bfloat16(v.y);
    __nv_bfloat16 h2 = __float2bfloat16(v.z), h3 = __float2bfloat16(v.w);
    __nv_bfloat16 l0 = __float2bfloat16(v.x - __bfloat162float(h0));
    __nv_bfloat16 l1 = __float2bfloat16(v.y - __bfloat162float(h1));
    __nv_bfloat16 l2 = __float2bfloat16(v.z - __bfloat162float(h2));
    __nv_bfloat16 l3 = __float2bfloat16(v.w - __bfloat162float(h3));
    ((uint2*)hi)[i] = make_uint2(pack_bf2(h0, h1), pack_bf2(h2, h3));
    ((uint2*)lo)[i] = make_uint2(pack_bf2(l0, l1), pack_bf2(l2, l3));
}

// =============== HMMA NT GEMM (split-bf16 emulated fp32) ===============
// C[m,n] = sum_k A[m,k]*B[n,k] + bias[n].  M = grid.y*128, N=1024, K=1024.
// A given as (Ahi, Alo) row-major [M,K]; B as (Bhi, Blo) row-major [N,K].
#define GK 1024
#define GN 1024

__global__ __launch_bounds__(256, 2)
void gemm_wmma(const __nv_bfloat16* __restrict__ Ahi, const __nv_bfloat16* __restrict__ Alo,
               const __nv_bfloat16* __restrict__ Bhi, const __nv_bfloat16* __restrict__ Blo,
               const float* __restrict__ bias, float* __restrict__ C) {
    __shared__ __nv_bfloat16 sAhi[128][24];
    __shared__ __nv_bfloat16 sAlo[128][24];
    __shared__ __nv_bfloat16 sBhi[128][24];
    __shared__ __nv_bfloat16 sBlo[128][24];

    int t = threadIdx.x;
    int m0 = blockIdx.y * 128, n0 = blockIdx.x * 128;
    int wid = t >> 5;
    int warp_m = wid & 1;      // 0..1 : 64 rows
    int warp_n = wid >> 1;     // 0..3 : 32 cols

    wmma::fragment<wmma::accumulator, 16, 16, 16, float> acc[4][2];
#pragma unroll
    for (int fm = 0; fm < 4; fm++)
#pragma unroll
        for (int fn = 0; fn < 2; fn++) wmma::fill_fragment(acc[fm][fn], 0.0f);

    int row = t >> 1, half = t & 1;   // each thread: one 8-elem chunk per matrix

    for (int ch = 0; ch < 64; ch++) {
        int k0 = ch * 16;
        __syncthreads();
        *(uint4*)&sAhi[row][half * 8] = *(const uint4*)&Ahi[(size_t)(m0 + row) * GK + k0 + half * 8];
        *(uint4*)&sAlo[row][half * 8] = *(const uint4*)&Alo[(size_t)(m0 + row) * GK + k0 + half * 8];
        *(uint4*)&sBhi[row][half * 8] = *(const uint4*)&Bhi[(size_t)(n0 + row) * GK + k0 + half * 8];
        *(uint4*)&sBlo[row][half * 8] = *(const uint4*)&Blo[(size_t)(n0 + row) * GK + k0 + half * 8];
        __syncthreads();

        wmma::fragment<wmma::matrix_b, 16, 16, 16, __nv_bfloat16, wmma::col_major> bh[2], bl[2];
#pragma unroll
        for (int fn = 0; fn < 2; fn++) {
            wmma::load_matrix_sync(bh[fn], &sBhi[warp_n * 32 + fn * 16][0], 24);
            wmma::load_matrix_sync(bl[fn], &sBlo[warp_n * 32 + fn * 16][0], 24);
        }
#pragma unroll
        for (int fm = 0; fm < 4; fm++) {
            wmma::fragment<wmma::matrix_a, 16, 16, 16, __nv_bfloat16, wmma::row_major> ah, al;
            wmma::load_matrix_sync(ah, &sAhi[warp_m * 64 + fm * 16][0], 24);
            wmma::load_matrix_sync(al, &sAlo[warp_m * 64 + fm * 16][0], 24);
#pragma unroll
            for (int fn = 0; fn < 2; fn++) {
                wmma::mma_sync(acc[fm][fn], ah, bh[fn], acc[fm][fn]);
                wmma::mma_sync(acc[fm][fn], ah, bl[fn], acc[fm][fn]);
                wmma::mma_sync(acc[fm][fn], al, bh[fn], acc[fm][fn]);
            }
        }
    }

    // bias as K-extension: A column of ones (hi), B column = split bias
    __syncthreads();
    {
        float bv = bias[n0 + row];
        __nv_bfloat16 bh_ = __float2bfloat16(bv);
        __nv_bfloat16 bl_ = __float2bfloat16(bv - __bfloat162float(bh_));
#pragma unroll
        for (int c = 0; c < 8; c++) {
            int col = half * 8 + c;
            sAhi[row][col] = (col == 0) ? __float2bfloat16(1.0f) : __float2bfloat16(0.0f);
            sAlo[row][col] = __float2bfloat16(0.0f);
            sBhi[row][col] = (col == 0) ? bh_ : __float2bfloat16(0.0f);
            sBlo[row][col] = (col == 0) ? bl_ : __float2bfloat16(0.0f);
        }
    }
    __syncthreads();
    {
        wmma::fragment<wmma::matrix_b, 16, 16, 16, __nv_bfloat16, wmma::col_major> bh[2], bl[2];
#pragma unroll
        for (int fn = 0; fn < 2; fn++) {
            wmma::load_matrix_sync(bh[fn], &sBhi[warp_n * 32 + fn * 16][0], 24);
            wmma::load_matrix_sync(bl[fn], &sBlo[warp_n * 32 + fn * 16][0], 24);
        }
#pragma unroll
        for (int fm = 0; fm < 4; fm++) {
            wmma::fragment<wmma::matrix_a, 16, 16, 16, __nv_bfloat16, wmma::row_major> ah;
            wmma::load_matrix_sync(ah, &sAhi[warp_m * 64 + fm * 16][0], 24);
#pragma unroll
            for (int fn = 0; fn < 2; fn++) {
                wmma::mma_sync(acc[fm][fn], ah, bh[fn], acc[fm][fn]);
                wmma::mma_sync(acc[fm][fn], ah, bl[fn], acc[fm][fn]);
            }
        }
    }

#pragma unroll
    for (int fm = 0; fm < 4; fm++)
#pragma unroll
        for (int fn = 0; fn < 2; fn++) {
            int m = m0 + warp_m * 64 + fm * 16;
            int n = n0 + warp_n * 32 + fn * 16;
            wmma::store_matrix_sync(&C[(size_t)m * GN + n], acc[fm][fn], GN, wmma::mem_row_major);
        }
}

// =============== banded QK scores ===============
__global__ void scores_kernel(const float* __restrict__ gamma,
                              const int*   __restrict__ ids,
                              const float* __restrict__ omega) {
    int x  = blockIdx.x;
    int it = blockIdx.y;
    int bh = blockIdx.z;
    if (x == 1 && it == 0) return;
    int b = bh / HH, h = bh % HH;
    int i0 = it * 64;
    int j0 = (it - x) * 64;

    __shared__ float Mtab[128];
    __shared__ float As[16][65];
    __shared__ float Bs[16][65];
    __shared__ int   idi[64], idj[64];

    int t  = threadIdx.x;
    int tx = t & 15, ty = t >> 4;

    if (t < 128) {
        float d  = (float)t;
        float ls = logf(d + 1.0f);
        float cs = 0.0f;
#pragma unroll
        for (int z = 0; z < NZ; z++) cs += cosf(gamma[z] * ls);
        Mtab[t] = expf(-d) * cs;
    }
    if (t < 64) {
        idi[t] = ids[b * SS + i0 + t];
        idj[t] = ids[b * SS + j0 + t];
    }

    const float* Aq = g_q + (size_t)(b * SS + i0) * DD + h * DK;
    const float* Bk = g_k + (size_t)(b * SS + j0) * DD + h * DK;

    float acc[4][4] = {};
    for (int k0 = 0; k0 < DK; k0 += 16) {
        __syncthreads();
#pragma unroll
        for (int r = 0; r < 4; r++) {
            int idx = t + r * 256;
            int mm = idx >> 4, kk = idx & 15;
            As[kk][mm] = Aq[(size_t)mm * DD + k0 + kk];
            Bs[kk][mm] = Bk[(size_t)mm * DD + k0 + kk];
        }
        __syncthreads();
#pragma unroll
        for (int kk = 0; kk < 16; kk++) {
            float a[4], bv[4];
#pragma unroll
            for (int r = 0; r < 4; r++) a[r] = As[kk][ty * 4 + r];
#pragma unroll
            for (int c = 0; c < 4; c++) bv[c] = Bs[kk][tx * 4 + c];
#pragma unroll
            for (int r = 0; r < 4; r++)
#pragma unroll
                for (int c = 0; c < 4; c++) acc[r][c] += a[r] * bv[c];
        }
    }
    __syncthreads();

    int coff = (1 - x) * 64;
#pragma unroll
    for (int r = 0; r < 4; r++) {
        int il = ty * 4 + r;
        int i  = i0 + il;
        float* dst = &g_sband[((size_t)bh * SS + i) * 128];
#pragma unroll
        for (int c = 0; c < 4; c++) {
            int jl = tx * 4 + c;
            int j  = j0 + jl;
            int ad = i - j; if (ad < 0) ad = -ad;
            float s = acc[r][c] * 0.125f * Mtab[ad];
            if (omega[(size_t)idi[il] * VV + idj[jl]] == 0.0f) s = -1.0e9f;
            dst[coff + jl] = s;
        }
    }
}

// =============== V chunk sums ===============
__global__ void vchunk_kernel() {
    int b  = blockIdx.x;
    int ch = blockIdx.y;
    int dc = blockIdx.z;
    int d  = dc * 256 + threadIdx.x;
    float acc = 0.0f;
    const float* base = g_v + ((size_t)b * SS + ch * 256) * DD + d;
#pragma unroll 8
    for (int j = 0; j < 256; j++) acc += base[(size_t)j * DD];
    g_csum[((size_t)b * 8 + ch) * DD + d] = acc;
}

// =============== V prefix sums ===============
__global__ void vpref_kernel() {
    int b  = blockIdx.x;
    int ch = blockIdx.y;
    int dc = blockIdx.z;
    int d  = dc * 256 + threadIdx.x;
    float acc = 0.0f;
    for (int c = 0; c < ch; c++) acc += g_csum[((size_t)b * 8 + c) * DD + d];
    const float* vbase = g_v + ((size_t)b * SS + ch * 256) * DD + d;
    float* pbase = g_pref + ((size_t)b * (SS + 1) + ch * 256) * DD + d;
    for (int j = 0; j < 256; j++) {
        pbase[(size_t)j * DD] = acc;
        acc += vbase[(size_t)j * DD];
    }
    if (ch == 7) g_pref[((size_t)b * (SS + 1) + SS) * DD + d] = acc;
}

// =============== far scan ===============
__global__ void farscan_kernel(const int* __restrict__ ids,
                               const float* __restrict__ omega) {
    int i = blockIdx.x;
    int b = blockIdx.y;
    int t = threadIdx.x;
    int lo = (i >> 6) * 64 - 64;
    int bandlo = lo < 0 ? 0 : lo;

    __shared__ float omg[VV];
    __shared__ int   list[1024];
    __shared__ int   cnt;

    int id_i = ids[b * SS + i];
    for (int dd = t; dd < VV; dd += 256) omg[dd] = omega[(size_t)id_i * VV + dd];
    if (t == 0) cnt = 0;
    __syncthreads();

    for (int j = t; j < bandlo; j += 256) {
        int idj = ids[b * SS + j];
        if (omg[idj] == 0.0f) {
            int p = atomicAdd(&cnt, 1);
            if (p < 1024) list[p] = j;
        }
    }
    __syncthreads();
    int n = cnt; if (n > 1024) n = 1024;

    float acc0 = 0.f, acc1 = 0.f, acc2 = 0.f, acc3 = 0.f;
    for (int l = 0; l < n; l++) {
        const float* vr = g_v + ((size_t)b * SS + list[l]) * DD;
        acc0 += vr[t];
        acc1 += vr[t + 256];
        acc2 += vr[t + 512];
        acc3 += vr[t + 768];
    }
    float* ms = g_msum + ((size_t)b * SS + i) * DD;
    ms[t]       = acc0;
    ms[t + 256] = acc1;
    ms[t + 512] = acc2;
    ms[t + 768] = acc3;
    if (t == 0) g_mcnt[b * SS + i] = n;
}

// =============== fused band softmax + band PV + far/tail correction ===============
extern __shared__ float dynsmem[];
__global__ void bandpv_kernel() {
    float* Sc = dynsmem;              // [128][68]
    float* Vb = dynsmem + 128 * 68;   // [128][68]
    __shared__ float red[256];
    __shared__ float m_s[64], inv_s[64], c0_s[64], wr_s[64];
    __shared__ float prefLo[64];

    int it = blockIdx.x;
    int bh = blockIdx.y;
    int b = bh >> 4, h = bh & 15;
    int lo_raw = it * 64 - 64;
    int bandlo = lo_raw < 0 ? 0 : lo_raw;
    int t = threadIdx.x;

    for (int idx = t; idx < 8192; idx += 256) {
        int r = idx >> 7, cc = idx & 127;
        int i = it * 64 + r;
        int j = lo_raw + cc;
        float s = -3.0e38f;
        if (j >= 0 && j <= i) s = g_sband[((size_t)bh * SS + i) * 128 + cc];
        Sc[cc * 68 + r] = s;
    }
    for (int idx = t; idx < 8192; idx += 256) {
        int cc = idx >> 6, d = idx & 63;
        int j = lo_raw + cc;
        float vv = 0.0f;
        if (j >= 0) vv = g_v[((size_t)(b * SS + j)) * DD + h * 64 + d];
        Vb[cc * 68 + d] = vv;
    }
    if (t < 64) prefLo[t] = g_pref[((size_t)b * (SS + 1) + bandlo) * DD + h * 64 + t];
    __syncthreads();

    int r = t & 63, q = t >> 6;
    float mx = -3.0e38f;
    for (int cc = q; cc < 128; cc += 4) mx = fmaxf(mx, Sc[cc * 68 + r]);
    red[t] = mx;
    __syncthreads();
    if (t < 64) {
        float m = fmaxf(fmaxf(red[r], red[64 + r]), fmaxf(red[128 + r], red[192 + r]));
        int i = it * 64 + r;
        int af = bandlo - g_mcnt[b * SS + i];
        if (af > 0) m = fmaxf(m, 0.0f);
        m_s[r] = m;
    }
    __syncthreads();

    float m = m_s[r];
    float zs = 0.0f;
    for (int cc = q; cc < 128; cc += 4) zs += expf(Sc[cc * 68 + r] - m);
    red[t] = zs;
    __syncthreads();
    if (t < 64) {
        float bsum = red[r] + red[64 + r] + red[128 + r] + red[192 + r];
        int i  = it * 64 + r;
        int mc = g_mcnt[b * SS + i];
        int af = bandlo - mc;
        float m0 = m_s[r];
        float wu = expf(-1.0e9f - m0);
        float Z  = bsum + (af > 0 ? (float)af * expf(-m0) : 0.0f)
                        + (float)(mc + (SS - 1 - i)) * wu;
        float inv = 1.0f / Z;
        inv_s[r] = inv;
        c0_s[r]  = (af > 0) ? expf(-m0) * inv : 0.0f;
        wr_s[r]  = wu * inv;
    }
    __syncthreads();

    for (int idx = t; idx < 8192; idx += 256) {
        int cc = idx >> 6, rr = idx & 63;
        Sc[cc * 68 + rr] = expf(Sc[cc * 68 + rr] - m_s[rr]) * inv_s[rr];
    }
    __syncthreads();

    int tx = t & 15, ty = t >> 4;
    float acc[4][4] = {};
#pragma unroll 4
    for (int cc = 0; cc < 128; cc++) {
        float4 w4 = *(const float4*)&Sc[cc * 68 + ty * 4];
        float4 v4 = *(const float4*)&Vb[cc * 68 + tx * 4];
        float wv[4] = {w4.x, w4.y, w4.z, w4.w};
        float vv[4] = {v4.x, v4.y, v4.z, v4.w};
#pragma unroll
        for (int rr = 0; rr < 4; rr++)
#pragma unroll
            for (int c = 0; c < 4; c++) acc[rr][c] += wv[rr] * vv[c];
    }

    const float* tv = g_pref + ((size_t)b * (SS + 1) + SS) * DD + h * 64;
#pragma unroll
    for (int rr = 0; rr < 4; rr++) {
        int rloc = ty * 4 + rr;
        int i = it * 64 + rloc;
        const float* ms = g_msum + ((size_t)b * SS + i) * DD + h * 64;
        const float* ph = g_pref + ((size_t)b * (SS + 1) + i + 1) * DD + h * 64;
        float c0 = c0_s[rloc], wr = wr_s[rloc];
        float* outp = g_ao + ((size_t)(b * SS + i)) * DD + h * 64;
#pragma unroll
        for (int c = 0; c < 4; c++) {
            int d = tx * 4 + c;
            float msv = ms[d];
            outp[d] = acc[rr][c] + c0 * (prefLo[d] - msv)
                                 + wr * (msv + tv[d] - ph[d]);
        }
    }
}

// ---------------- launcher ----------------
extern "C" void kernel_launch(void* const* d_in, const int* in_sizes, int n_in,
                              void* d_out, int out_size) {
    const float* x     = (const float*)d_in[0];
    const float* wq    = (const float*)d_in[1];
    const float* bq    = (const float*)d_in[2];
    const float* wk    = (const float*)d_in[3];
    const float* bk    = (const float*)d_in[4];
    const float* wv    = (const float*)d_in[5];
    const float* bv    = (const float*)d_in[6];
    const float* wo    = (const float*)d_in[7];
    const float* bo    = (const float*)d_in[8];
    const float* omega = (const float*)d_in[9];
    const float* gamma = (const float*)d_in[10];
    const int*   ids   = (const int*)d_in[11];
    float* out = (float*)d_out;

    float *pq, *pk, *pv, *pao;
    cudaGetSymbolAddress((void**)&pq,  g_q);
    cudaGetSymbolAddress((void**)&pk,  g_k);
    cudaGetSymbolAddress((void**)&pv,  g_v);
    cudaGetSymbolAddress((void**)&pao, g_ao);
    __nv_bfloat16 *xhi, *xlo, *whi, *wlo, *aohi, *aolo;
    cudaGetSymbolAddress((void**)&xhi,  g_xhi);
    cudaGetSymbolAddress((void**)&xlo,  g_xlo);
    cudaGetSymbolAddress((void**)&whi,  g_whi);
    cudaGetSymbolAddress((void**)&wlo,  g_wlo);
    cudaGetSymbolAddress((void**)&aohi, g_aohi);
    cudaGetSymbolAddress((void**)&aolo, g_aolo);

    cudaFuncSetAttribute(bandpv_kernel,
                         cudaFuncAttributeMaxDynamicSharedMemorySize,
                         2 * 128 * 68 * (int)sizeof(float));

    dim3 blk(256);
    const int WN4 = DD * DD / 4;       // 262144 (one weight, float4 units)
    const int XN4 = MROWS * DD / 4;    // 1048576

    // splits: x and the four weights
    split_kernel<<<XN4 / 256, blk>>>(x, xhi, xlo, XN4);
    split_kernel<<<WN4 / 256, blk>>>(wq, whi + 0 * DD * DD, wlo + 0 * DD * DD, WN4);
    split_kernel<<<WN4 / 256, blk>>>(wk, whi + 1 * DD * DD, wlo + 1 * DD * DD, WN4);
    split_kernel<<<WN4 / 256, blk>>>(wv, whi + 2 * DD * DD, wlo + 2 * DD * DD, WN4);
    split_kernel<<<WN4 / 256, blk>>>(wo, whi + 3 * DD * DD, wlo + 3 * DD * DD, WN4);

    dim3 gproj(DD / 128, MROWS / 128);   // (8, 32)

    // Q, K, V projections on HMMA tensor cores
    gemm_wmma<<<gproj, blk>>>(xhi, xlo, whi + 0 * DD * DD, wlo + 0 * DD * DD, bq, pq);
    gemm_wmma<<<gproj, blk>>>(xhi, xlo, whi + 1 * DD * DD, wlo + 1 * DD * DD, bk, pk);
    gemm_wmma<<<gproj, blk>>>(xhi, xlo, whi + 2 * DD * DD, wlo + 2 * DD * DD, bv, pv);

    // Banded scores
    dim3 gsc(2, SS / 64, BH);
    scores_kernel<<<gsc, blk>>>(gamma, ids, omega);

    // V prefix sums
    vchunk_kernel<<<dim3(BB, 8, 4), blk>>>();
    vpref_kernel <<<dim3(BB, 8, 4), blk>>>();

    // Far-mask scan
    farscan_kernel<<<dim3(SS, BB), blk>>>(ids, omega);

    // Fused band softmax + PV + far/tail corrections
    bandpv_kernel<<<dim3(SS / 64, BH), blk, 2 * 128 * 68 * sizeof(float)>>>();

    // Output projection
    split_kernel<<<XN4 / 256, blk>>>(pao, aohi, aolo, XN4);
    gemm_wmma<<<gproj, blk>>>(aohi, aolo, whi + 3 * DD * DD, wlo + 3 * DD * DD, bo, out);
}

// round 5
// speedup vs baseline: 3.5066x; 1.0005x over previous
#include <cuda_runtime.h>
#include <cuda_bf16.h>
#include <mma.h>
#include <math.h>
#include <stdint.h>

using namespace nvcuda;

// Problem constants
#define BB   2
#define SS   2048
#define DD   1024
#define HH   16
#define DK   64
#define VV   4096
#define NZ   10
#define BH   (BB*HH)      // 32
#define MROWS (BB*SS)     // 4096

// ---------------- scratch (device globals: allocation-free) ----------------
__device__ float g_q   [MROWS*DD];                 // 16 MB
__device__ float g_k   [MROWS*DD];                 // 16 MB
__device__ float g_v   [MROWS*DD];                 // 16 MB
__device__ float g_ao  [MROWS*DD];                 // 16 MB
__device__ float g_sband[BH*SS*128];               // 32 MB (banded scores)
__device__ float g_pref [(size_t)BB*(SS+1)*DD];    // 16.8 MB (exclusive prefix of v)
__device__ float g_csum [BB*8*DD];                 // chunk sums
__device__ float g_msum [(size_t)BB*SS*DD];        // 16 MB masked-far v sums
__device__ int   g_mcnt [BB*SS];                   // masked-far counts

// split bf16 hi/lo copies
__device__ __nv_bfloat16 g_xhi [MROWS*DD];         // 8 MB
__device__ __nv_bfloat16 g_xlo [MROWS*DD];         // 8 MB
__device__ __nv_bfloat16 g_whi [4*DD*DD];          // 8 MB (wq,wk,wv,wo stacked)
__device__ __nv_bfloat16 g_wlo [4*DD*DD];          // 8 MB
__device__ __nv_bfloat16 g_aohi[MROWS*DD];         // 8 MB
__device__ __nv_bfloat16 g_aolo[MROWS*DD];         // 8 MB

__device__ __forceinline__ uint32_t pack_bf2(__nv_bfloat16 a, __nv_bfloat16 b) {
    return ((uint32_t)__bfloat16_as_ushort(b) << 16) | (uint32_t)__bfloat16_as_ushort(a);
}

// =============== split fp32 -> bf16 hi + bf16 lo ===============
__global__ void split_kernel(const float* __restrict__ in,
                             __nv_bfloat16* __restrict__ hi,
                             __nv_bfloat16* __restrict__ lo, int n4) {
    int i = blockIdx.x * blockDim.x + threadIdx.x;
    if (i >= n4) return;
    float4 v = ((const float4*)in)[i];
    __nv_bfloat16 h0 = __float2bfloat16(v.x), h1 = __float2bfloat16(v.y);
    __nv_bfloat16 h2 = __float2bfloat16(v.z), h3 = __float2bfloat16(v.w);
    __nv_bfloat16 l0 = __float2bfloat16(v.x - __bfloat162float(h0));
    __nv_bfloat16 l1 = __float2bfloat16(v.y - __bfloat162float(h1));
    __nv_bfloat16 l2 = __float2bfloat16(v.z - __bfloat162float(h2));
    __nv_bfloat16 l3 = __float2bfloat16(v.w - __bfloat162float(h3));
    ((uint2*)hi)[i] = make_uint2(pack_bf2(h0, h1), pack_bf2(h2, h3));
    ((uint2*)lo)[i] = make_uint2(pack_bf2(l0, l1), pack_bf2(l2, l3));
}

// =============== HMMA NT GEMM (split-bf16 emulated fp32) ===============
// C[m,n] = sum_k A[m,k]*B[n,k] + bias[n].  M = grid.y*128, N=1024, K=1024.
// A given as (Ahi, Alo) row-major [M,K]; B as (Bhi, Blo) row-major [N,K].
#define GK 1024
#define GN 1024

__global__ __launch_bounds__(256, 2)
void gemm_wmma(const __nv_bfloat16* __restrict__ Ahi, const __nv_bfloat16* __restrict__ Alo,
               const __nv_bfloat16* __restrict__ Bhi, const __nv_bfloat16* __restrict__ Blo,
               const float* __restrict__ bias, float* __restrict__ C) {
    __shared__ __nv_bfloat16 sAhi[128][24];
    __shared__ __nv_bfloat16 sAlo[128][24];
    __shared__ __nv_bfloat16 sBhi[128][24];
    __shared__ __nv_bfloat16 sBlo[128][24];

    int t = threadIdx.x;
    int m0 = blockIdx.y * 128, n0 = blockIdx.x * 128;
    int wid = t >> 5;
    int warp_m = wid & 1;      // 0..1 : 64 rows
    int warp_n = wid >> 1;     // 0..3 : 32 cols

    wmma::fragment<wmma::accumulator, 16, 16, 16, float> acc[4][2];
#pragma unroll
    for (int fm = 0; fm < 4; fm++)
#pragma unroll
        for (int fn = 0; fn < 2; fn++) wmma::fill_fragment(acc[fm][fn], 0.0f);

    int row = t >> 1, half = t & 1;   // each thread: one 8-elem chunk per matrix

    for (int ch = 0; ch < 64; ch++) {
        int k0 = ch * 16;
        __syncthreads();
        *(uint4*)&sAhi[row][half * 8] = *(const uint4*)&Ahi[(size_t)(m0 + row) * GK + k0 + half * 8];
        *(uint4*)&sAlo[row][half * 8] = *(const uint4*)&Alo[(size_t)(m0 + row) * GK + k0 + half * 8];
        *(uint4*)&sBhi[row][half * 8] = *(const uint4*)&Bhi[(size_t)(n0 + row) * GK + k0 + half * 8];
        *(uint4*)&sBlo[row][half * 8] = *(const uint4*)&Blo[(size_t)(n0 + row) * GK + k0 + half * 8];
        __syncthreads();

        wmma::fragment<wmma::matrix_b, 16, 16, 16, __nv_bfloat16, wmma::col_major> bh[2], bl[2];
#pragma unroll
        for (int fn = 0; fn < 2; fn++) {
            wmma::load_matrix_sync(bh[fn], &sBhi[warp_n * 32 + fn * 16][0], 24);
            wmma::load_matrix_sync(bl[fn], &sBlo[warp_n * 32 + fn * 16][0], 24);
        }
#pragma unroll
        for (int fm = 0; fm < 4; fm++) {
            wmma::fragment<wmma::matrix_a, 16, 16, 16, __nv_bfloat16, wmma::row_major> ah, al;
            wmma::load_matrix_sync(ah, &sAhi[warp_m * 64 + fm * 16][0], 24);
            wmma::load_matrix_sync(al, &sAlo[warp_m * 64 + fm * 16][0], 24);
#pragma unroll
            for (int fn = 0; fn < 2; fn++) {
                wmma::mma_sync(acc[fm][fn], ah, bh[fn], acc[fm][fn]);
                wmma::mma_sync(acc[fm][fn], ah, bl[fn], acc[fm][fn]);
                wmma::mma_sync(acc[fm][fn], al, bh[fn], acc[fm][fn]);
            }
        }
    }

    // bias as K-extension: A column of ones (hi), B column = split bias
    __syncthreads();
    {
        float bv = bias[n0 + row];
        __nv_bfloat16 bh_ = __float2bfloat16(bv);
        __nv_bfloat16 bl_ = __float2bfloat16(bv - __bfloat162float(bh_));
#pragma unroll
        for (int c = 0; c < 8; c++) {
            int col = half * 8 + c;
            sAhi[row][col] = (col == 0) ? __float2bfloat16(1.0f) : __float2bfloat16(0.0f);
            sAlo[row][col] = __float2bfloat16(0.0f);
            sBhi[row][col] = (col == 0) ? bh_ : __float2bfloat16(0.0f);
            sBlo[row][col] = (col == 0) ? bl_ : __float2bfloat16(0.0f);
        }
    }
    __syncthreads();
    {
        wmma::fragment<wmma::matrix_b, 16, 16, 16, __nv_bfloat16, wmma::col_major> bh[2], bl[2];
#pragma unroll
        for (int fn = 0; fn < 2; fn++) {
            wmma::load_matrix_sync(bh[fn], &sBhi[warp_n * 32 + fn * 16][0], 24);
            wmma::load_matrix_sync(bl[fn], &sBlo[warp_n * 32 + fn * 16][0], 24);
        }
#pragma unroll
        for (int fm = 0; fm < 4; fm++) {
            wmma::fragment<wmma::matrix_a, 16, 16, 16, __nv_bfloat16, wmma::row_major> ah;
            wmma::load_matrix_sync(ah, &sAhi[warp_m * 64 + fm * 16][0], 24);
#pragma unroll
            for (int fn = 0; fn < 2; fn++) {
                wmma::mma_sync(acc[fm][fn], ah, bh[fn], acc[fm][fn]);
                wmma::mma_sync(acc[fm][fn], ah, bl[fn], acc[fm][fn]);
            }
        }
    }

#pragma unroll
    for (int fm = 0; fm < 4; fm++)
#pragma unroll
        for (int fn = 0; fn < 2; fn++) {
            int m = m0 + warp_m * 64 + fm * 16;
            int n = n0 + warp_n * 32 + fn * 16;
            wmma::store_matrix_sync(&C[(size_t)m * GN + n], acc[fm][fn], GN, wmma::mem_row_major);
        }
}

// =============== banded QK scores ===============
__global__ void scores_kernel(const float* __restrict__ gamma,
                              const int*   __restrict__ ids,
                              const float* __restrict__ omega) {
    int x  = blockIdx.x;
    int it = blockIdx.y;
    int bh = blockIdx.z;
    if (x == 1 && it == 0) return;
    int b = bh / HH, h = bh % HH;
    int i0 = it * 64;
    int j0 = (it - x) * 64;

    __shared__ float Mtab[128];
    __shared__ float As[16][65];
    __shared__ float Bs[16][65];
    __shared__ int   idi[64], idj[64];

    int t  = threadIdx.x;
    int tx = t & 15, ty = t >> 4;

    if (t < 128) {
        float d  = (float)t;
        float ls = logf(d + 1.0f);
        float cs = 0.0f;
#pragma unroll
        for (int z = 0; z < NZ; z++) cs += cosf(gamma[z] * ls);
        Mtab[t] = expf(-d) * cs;
    }
    if (t < 64) {
        idi[t] = ids[b * SS + i0 + t];
        idj[t] = ids[b * SS + j0 + t];
    }

    const float* Aq = g_q + (size_t)(b * SS + i0) * DD + h * DK;
    const float* Bk = g_k + (size_t)(b * SS + j0) * DD + h * DK;

    float acc[4][4] = {};
    for (int k0 = 0; k0 < DK; k0 += 16) {
        __syncthreads();
#pragma unroll
        for (int r = 0; r < 4; r++) {
            int idx = t + r * 256;
            int mm = idx >> 4, kk = idx & 15;
            As[kk][mm] = Aq[(size_t)mm * DD + k0 + kk];
            Bs[kk][mm] = Bk[(size_t)mm * DD + k0 + kk];
        }
        __syncthreads();
#pragma unroll
        for (int kk = 0; kk < 16; kk++) {
            float a[4], bv[4];
#pragma unroll
            for (int r = 0; r < 4; r++) a[r] = As[kk][ty * 4 + r];
#pragma unroll
            for (int c = 0; c < 4; c++) bv[c] = Bs[kk][tx * 4 + c];
#pragma unroll
            for (int r = 0; r < 4; r++)
#pragma unroll
                for (int c = 0; c < 4; c++) acc[r][c] += a[r] * bv[c];
        }
    }
    __syncthreads();

    int coff = (1 - x) * 64;
#pragma unroll
    for (int r = 0; r < 4; r++) {
        int il = ty * 4 + r;
        int i  = i0 + il;
        float* dst = &g_sband[((size_t)bh * SS + i) * 128];
#pragma unroll
        for (int c = 0; c < 4; c++) {
            int jl = tx * 4 + c;
            int j  = j0 + jl;
            int ad = i - j; if (ad < 0) ad = -ad;
            float s = acc[r][c] * 0.125f * Mtab[ad];
            if (omega[(size_t)idi[il] * VV + idj[jl]] == 0.0f) s = -1.0e9f;
            dst[coff + jl] = s;
        }
    }
}

// =============== V chunk sums ===============
__global__ void vchunk_kernel() {
    int b  = blockIdx.x;
    int ch = blockIdx.y;
    int dc = blockIdx.z;
    int d  = dc * 256 + threadIdx.x;
    float acc = 0.0f;
    const float* base = g_v + ((size_t)b * SS + ch * 256) * DD + d;
#pragma unroll 8
    for (int j = 0; j < 256; j++) acc += base[(size_t)j * DD];
    g_csum[((size_t)b * 8 + ch) * DD + d] = acc;
}

// =============== V prefix sums ===============
__global__ void vpref_kernel() {
    int b  = blockIdx.x;
    int ch = blockIdx.y;
    int dc = blockIdx.z;
    int d  = dc * 256 + threadIdx.x;
    float acc = 0.0f;
    for (int c = 0; c < ch; c++) acc += g_csum[((size_t)b * 8 + c) * DD + d];
    const float* vbase = g_v + ((size_t)b * SS + ch * 256) * DD + d;
    float* pbase = g_pref + ((size_t)b * (SS + 1) + ch * 256) * DD + d;
    for (int j = 0; j < 256; j++) {
        pbase[(size_t)j * DD] = acc;
        acc += vbase[(size_t)j * DD];
    }
    if (ch == 7) g_pref[((size_t)b * (SS + 1) + SS) * DD + d] = acc;
}

// =============== far scan ===============
__global__ void farscan_kernel(const int* __restrict__ ids,
                               const float* __restrict__ omega) {
    int i = blockIdx.x;
    int b = blockIdx.y;
    int t = threadIdx.x;
    int lo = (i >> 6) * 64 - 64;
    int bandlo = lo < 0 ? 0 : lo;

    __shared__ float omg[VV];
    __shared__ int   list[1024];
    __shared__ int   cnt;

    int id_i = ids[b * SS + i];
    for (int dd = t; dd < VV; dd += 256) omg[dd] = omega[(size_t)id_i * VV + dd];
    if (t == 0) cnt = 0;
    __syncthreads();

    for (int j = t; j < bandlo; j += 256) {
        int idj = ids[b * SS + j];
        if (omg[idj] == 0.0f) {
            int p = atomicAdd(&cnt, 1);
            if (p < 1024) list[p] = j;
        }
    }
    __syncthreads();
    int n = cnt; if (n > 1024) n = 1024;

    float acc0 = 0.f, acc1 = 0.f, acc2 = 0.f, acc3 = 0.f;
    for (int l = 0; l < n; l++) {
        const float* vr = g_v + ((size_t)b * SS + list[l]) * DD;
        acc0 += vr[t];
        acc1 += vr[t + 256];
        acc2 += vr[t + 512];
        acc3 += vr[t + 768];
    }
    float* ms = g_msum + ((size_t)b * SS + i) * DD;
    ms[t]       = acc0;
    ms[t + 256] = acc1;
    ms[t + 512] = acc2;
    ms[t + 768] = acc3;
    if (t == 0) g_mcnt[b * SS + i] = n;
}

// =============== fused band softmax + band PV + far/tail correction ===============
extern __shared__ float dynsmem[];
__global__ void bandpv_kernel() {
    float* Sc = dynsmem;              // [128][68]
    float* Vb = dynsmem + 128 * 68;   // [128][68]
    __shared__ float red[256];
    __shared__ float m_s[64], inv_s[64], c0_s[64], wr_s[64];
    __shared__ float prefLo[64];

    int it = blockIdx.x;
    int bh = blockIdx.y;
    int b = bh >> 4, h = bh & 15;
    int lo_raw = it * 64 - 64;
    int bandlo = lo_raw < 0 ? 0 : lo_raw;
    int t = threadIdx.x;

    for (int idx = t; idx < 8192; idx += 256) {
        int r = idx >> 7, cc = idx & 127;
        int i = it * 64 + r;
        int j = lo_raw + cc;
        float s = -3.0e38f;
        if (j >= 0 && j <= i) s = g_sband[((size_t)bh * SS + i) * 128 + cc];
        Sc[cc * 68 + r] = s;
    }
    for (int idx = t; idx < 8192; idx += 256) {
        int cc = idx >> 6, d = idx & 63;
        int j = lo_raw + cc;
        float vv = 0.0f;
        if (j >= 0) vv = g_v[((size_t)(b * SS + j)) * DD + h * 64 + d];
        Vb[cc * 68 + d] = vv;
    }
    if (t < 64) prefLo[t] = g_pref[((size_t)b * (SS + 1) + bandlo) * DD + h * 64 + t];
    __syncthreads();

    int r = t & 63, q = t >> 6;
    float mx = -3.0e38f;
    for (int cc = q; cc < 128; cc += 4) mx = fmaxf(mx, Sc[cc * 68 + r]);
    red[t] = mx;
    __syncthreads();
    if (t < 64) {
        float m = fmaxf(fmaxf(red[r], red[64 + r]), fmaxf(red[128 + r], red[192 + r]));
        int i = it * 64 + r;
        int af = bandlo - g_mcnt[b * SS + i];
        if (af > 0) m = fmaxf(m, 0.0f);
        m_s[r] = m;
    }
    __syncthreads();

    float m = m_s[r];
    float zs = 0.0f;
    for (int cc = q; cc < 128; cc += 4) zs += expf(Sc[cc * 68 + r] - m);
    red[t] = zs;
    __syncthreads();
    if (t < 64) {
        float bsum = red[r] + red[64 + r] + red[128 + r] + red[192 + r];
        int i  = it * 64 + r;
        int mc = g_mcnt[b * SS + i];
        int af = bandlo - mc;
        float m0 = m_s[r];
        float wu = expf(-1.0e9f - m0);
        float Z  = bsum + (af > 0 ? (float)af * expf(-m0) : 0.0f)
                        + (float)(mc + (SS - 1 - i)) * wu;
        float inv = 1.0f / Z;
        inv_s[r] = inv;
        c0_s[r]  = (af > 0) ? expf(-m0) * inv : 0.0f;
        wr_s[r]  = wu * inv;
    }
    __syncthreads();

    for (int idx = t; idx < 8192; idx += 256) {
        int cc = idx >> 6, rr = idx & 63;
        Sc[cc * 68 + rr] = expf(Sc[cc * 68 + rr] - m_s[rr]) * inv_s[rr];
    }
    __syncthreads();

    int tx = t & 15, ty = t >> 4;
    float acc[4][4] = {};
#pragma unroll 4
    for (int cc = 0; cc < 128; cc++) {
        float4 w4 = *(const float4*)&Sc[cc * 68 + ty * 4];
        float4 v4 = *(const float4*)&Vb[cc * 68 + tx * 4];
        float wv[4] = {w4.x, w4.y, w4.z, w4.w};
        float vv[4] = {v4.x, v4.y, v4.z, v4.w};
#pragma unroll
        for (int rr = 0; rr < 4; rr++)
#pragma unroll
            for (int c = 0; c < 4; c++) acc[rr][c] += wv[rr] * vv[c];
    }

    const float* tv = g_pref + ((size_t)b * (SS + 1) + SS) * DD + h * 64;
#pragma unroll
    for (int rr = 0; rr < 4; rr++) {
        int rloc = ty * 4 + rr;
        int i = it * 64 + rloc;
        const float* ms = g_msum + ((size_t)b * SS + i) * DD + h * 64;
        const float* ph = g_pref + ((size_t)b * (SS + 1) + i + 1) * DD + h * 64;
        float c0 = c0_s[rloc], wr = wr_s[rloc];
        float* outp = g_ao + ((size_t)(b * SS + i)) * DD + h * 64;
#pragma unroll
        for (int c = 0; c < 4; c++) {
            int d = tx * 4 + c;
            float msv = ms[d];
            outp[d] = acc[rr][c] + c0 * (prefLo[d] - msv)
                                 + wr * (msv + tv[d] - ph[d]);
        }
    }
}

// ---------------- launcher ----------------
extern "C" void kernel_launch(void* const* d_in, const int* in_sizes, int n_in,
                              void* d_out, int out_size) {
    const float* x     = (const float*)d_in[0];
    const float* wq    = (const float*)d_in[1];
    const float* bq    = (const float*)d_in[2];
    const float* wk    = (const float*)d_in[3];
    const float* bk    = (const float*)d_in[4];
    const float* wv    = (const float*)d_in[5];
    const float* bv    = (const float*)d_in[6];
    const float* wo    = (const float*)d_in[7];
    const float* bo    = (const float*)d_in[8];
    const float* omega = (const float*)d_in[9];
    const float* gamma = (const float*)d_in[10];
    const int*   ids   = (const int*)d_in[11];
    float* out = (float*)d_out;

    float *pq, *pk, *pv, *pao;
    cudaGetSymbolAddress((void**)&pq,  g_q);
    cudaGetSymbolAddress((void**)&pk,  g_k);
    cudaGetSymbolAddress((void**)&pv,  g_v);
    cudaGetSymbolAddress((void**)&pao, g_ao);
    __nv_bfloat16 *xhi, *xlo, *whi, *wlo, *aohi, *aolo;
    cudaGetSymbolAddress((void**)&xhi,  g_xhi);
    cudaGetSymbolAddress((void**)&xlo,  g_xlo);
    cudaGetSymbolAddress((void**)&whi,  g_whi);
    cudaGetSymbolAddress((void**)&wlo,  g_wlo);
    cudaGetSymbolAddress((void**)&aohi, g_aohi);
    cudaGetSymbolAddress((void**)&aolo, g_aolo);

    cudaFuncSetAttribute(bandpv_kernel,
                         cudaFuncAttributeMaxDynamicSharedMemorySize,
                         2 * 128 * 68 * (int)sizeof(float));

    dim3 blk(256);
    const int WN4 = DD * DD / 4;       // 262144 (one weight, float4 units)
    const int XN4 = MROWS * DD / 4;    // 1048576

    // splits: x and the four weights
    split_kernel<<<XN4 / 256, blk>>>(x, xhi, xlo, XN4);
    split_kernel<<<WN4 / 256, blk>>>(wq, whi + 0 * DD * DD, wlo + 0 * DD * DD, WN4);
    split_kernel<<<WN4 / 256, blk>>>(wk, whi + 1 * DD * DD, wlo + 1 * DD * DD, WN4);
    split_kernel<<<WN4 / 256, blk>>>(wv, whi + 2 * DD * DD, wlo + 2 * DD * DD, WN4);
    split_kernel<<<WN4 / 256, blk>>>(wo, whi + 3 * DD * DD, wlo + 3 * DD * DD, WN4);

    dim3 gproj(DD / 128, MROWS / 128);   // (8, 32)

    // Q, K, V projections on HMMA tensor cores
    gemm_wmma<<<gproj, blk>>>(xhi, xlo, whi + 0 * DD * DD, wlo + 0 * DD * DD, bq, pq);
    gemm_wmma<<<gproj, blk>>>(xhi, xlo, whi + 1 * DD * DD, wlo + 1 * DD * DD, bk, pk);
    gemm_wmma<<<gproj, blk>>>(xhi, xlo, whi + 2 * DD * DD, wlo + 2 * DD * DD, bv, pv);

    // Banded scores
    dim3 gsc(2, SS / 64, BH);
    scores_kernel<<<gsc, blk>>>(gamma, ids, omega);

    // V prefix sums
    vchunk_kernel<<<dim3(BB, 8, 4), blk>>>();
    vpref_kernel <<<dim3(BB, 8, 4), blk>>>();

    // Far-mask scan
    farscan_kernel<<<dim3(SS, BB), blk>>>(ids, omega);

    // Fused band softmax + PV + far/tail corrections
    bandpv_kernel<<<dim3(SS / 64, BH), blk, 2 * 128 * 68 * sizeof(float)>>>();

    // Output projection
    split_kernel<<<XN4 / 256, blk>>>(pao, aohi, aolo, XN4);
    gemm_wmma<<<gproj, blk>>>(aohi, aolo, whi + 3 * DD * DD, wlo + 3 * DD * DD, bo, out);
}